// round 8
// baseline (speedup 1.0000x reference)
#include <cuda_runtime.h>

// Noisy LIF spiking neuron scan — R7: 256-bit vector memory ops (sm_100+).
//   u = 0.5*u + x[t] - 0.5*noise[t] ; o = (u > 1) ; u = o ? 0 : u
//
// R1-R6 pinned the float4 structural optimum at DRAM=84.1% / 115us ncu
// (plain rolled loop, regs=28; __stwt lost; CH-batching lost). This round
// swaps float4 -> float8 via ld/st.global.v8.f32: half the LDG/STG
// instructions, 2x bytes per L1tex wavefront-queue entry at fixed warp
// count. One thread owns 8 adjacent lanes; 131072 threads, 512 CTAs x 256.

static constexpr int B  = 16;
static constexpr int T  = 64;
static constexpr int N  = 65536;
static constexpr int N8 = N / 8;     // float8 lanes per (b, t) row = 8192

__device__ __forceinline__ void ldg256(const float* p, float* v) {
    asm volatile(
        "ld.global.v8.f32 {%0, %1, %2, %3, %4, %5, %6, %7}, [%8];"
        : "=f"(v[0]), "=f"(v[1]), "=f"(v[2]), "=f"(v[3]),
          "=f"(v[4]), "=f"(v[5]), "=f"(v[6]), "=f"(v[7])
        : "l"(p));
}

__device__ __forceinline__ void stg256(float* p, const float* v) {
    asm volatile(
        "st.global.v8.f32 [%0], {%1, %2, %3, %4, %5, %6, %7, %8};"
        :: "l"(p),
           "f"(v[0]), "f"(v[1]), "f"(v[2]), "f"(v[3]),
           "f"(v[4]), "f"(v[5]), "f"(v[6]), "f"(v[7])
        : "memory");
}

__global__ __launch_bounds__(256) void lif_kernel(
    const float* __restrict__ x,
    const float* __restrict__ noise,
    float* __restrict__ out)
{
    int idx = blockIdx.x * blockDim.x + threadIdx.x;   // 0 .. B*N8-1 (exact)

    int b  = idx >> 13;          // / N8 (8192)
    int n8 = idx & (N8 - 1);     // % N8

    const size_t base = (size_t)b * T * N + (size_t)n8 * 8;
    const float* __restrict__ xp = x     + base;
    const float* __restrict__ np = noise + base;
    float*       __restrict__ op = out   + base;

    float u[8];
#pragma unroll
    for (int i = 0; i < 8; i++) u[i] = 0.f;

#pragma unroll
    for (int t = 0; t < T; t++) {
        float xv[8], nv[8], o[8];
        ldg256(xp + (size_t)t * N, xv);
        ldg256(np + (size_t)t * N, nv);

#pragma unroll
        for (int i = 0; i < 8; i++) {
            u[i] = fmaf(-0.5f, nv[i], fmaf(0.5f, u[i], xv[i]));
            o[i] = (u[i] > 1.0f) ? 1.0f : 0.0f;
            u[i] = (u[i] > 1.0f) ? 0.0f : u[i];
        }

        stg256(op + (size_t)t * N, o);
    }
}

extern "C" void kernel_launch(void* const* d_in, const int* in_sizes, int n_in,
                              void* d_out, int out_size)
{
    const float* x     = (const float*)d_in[0];
    const float* noise = (const float*)d_in[1];
    float*       out   = (float*)d_out;

    const int total_threads = B * N8;        // 131072
    const int tpb = 256;
    const int blocks = total_threads / tpb;  // 512, exact

    lif_kernel<<<blocks, tpb>>>(x, noise, out);
}

// round 10
// speedup vs baseline: 1.0018x; 1.0018x over previous
#include <cuda_runtime.h>

// Noisy LIF spiking neuron scan — R8: v8 (256-bit) memory ops + finer grid.
//   u = 0.5*u + x[t] - 0.5*noise[t] ; o = (u > 1) ; u = o ? 0 : u
//
// R7 (v8, tpb=256, 512 CTAs) set the ncu record: DRAM=84.8%, 114.2us.
// occ 40.5% is thread-count-limited (131072 threads total, single wave);
// grid=512 gives 4-vs-3 CTAs/SM imbalance (33% per-SM work skew).
// R8: identical body, tpb=128 -> 1024 CTAs -> 7-vs-6 per SM (17% skew,
// 1-in-7 granularity) to shrink the wave tail.

static constexpr int B  = 16;
static constexpr int T  = 64;
static constexpr int N  = 65536;
static constexpr int N8 = N / 8;     // float8 lanes per (b, t) row = 8192

__device__ __forceinline__ void ldg256(const float* p, float* v) {
    asm volatile(
        "ld.global.v8.f32 {%0, %1, %2, %3, %4, %5, %6, %7}, [%8];"
        : "=f"(v[0]), "=f"(v[1]), "=f"(v[2]), "=f"(v[3]),
          "=f"(v[4]), "=f"(v[5]), "=f"(v[6]), "=f"(v[7])
        : "l"(p));
}

__device__ __forceinline__ void stg256(float* p, const float* v) {
    asm volatile(
        "st.global.v8.f32 [%0], {%1, %2, %3, %4, %5, %6, %7, %8};"
        :: "l"(p),
           "f"(v[0]), "f"(v[1]), "f"(v[2]), "f"(v[3]),
           "f"(v[4]), "f"(v[5]), "f"(v[6]), "f"(v[7])
        : "memory");
}

__global__ __launch_bounds__(128) void lif_kernel(
    const float* __restrict__ x,
    const float* __restrict__ noise,
    float* __restrict__ out)
{
    int idx = blockIdx.x * blockDim.x + threadIdx.x;   // 0 .. B*N8-1 (exact)

    int b  = idx >> 13;          // / N8 (8192)
    int n8 = idx & (N8 - 1);     // % N8

    const size_t base = (size_t)b * T * N + (size_t)n8 * 8;
    const float* __restrict__ xp = x     + base;
    const float* __restrict__ np = noise + base;
    float*       __restrict__ op = out   + base;

    float u[8];
#pragma unroll
    for (int i = 0; i < 8; i++) u[i] = 0.f;

#pragma unroll
    for (int t = 0; t < T; t++) {
        float xv[8], nv[8], o[8];
        ldg256(xp + (size_t)t * N, xv);
        ldg256(np + (size_t)t * N, nv);

#pragma unroll
        for (int i = 0; i < 8; i++) {
            u[i] = fmaf(-0.5f, nv[i], fmaf(0.5f, u[i], xv[i]));
            o[i] = (u[i] > 1.0f) ? 1.0f : 0.0f;
            u[i] = (u[i] > 1.0f) ? 0.0f : u[i];
        }

        stg256(op + (size_t)t * N, o);
    }
}

extern "C" void kernel_launch(void* const* d_in, const int* in_sizes, int n_in,
                              void* d_out, int out_size)
{
    const float* x     = (const float*)d_in[0];
    const float* noise = (const float*)d_in[1];
    float*       out   = (float*)d_out;

    const int total_threads = B * N8;        // 131072
    const int tpb = 128;
    const int blocks = total_threads / tpb;  // 1024, exact

    lif_kernel<<<blocks, tpb>>>(x, noise, out);
}

// round 11
// speedup vs baseline: 1.0048x; 1.0030x over previous
#include <cuda_runtime.h>

// Noisy LIF spiking neuron scan — R9: v8 256-bit ops (R7 record config)
// + .cs streaming cache hints.
//   u = 0.5*u + x[t] - 0.5*noise[t] ; o = (u > 1) ; u = o ? 0 : u
//
// R7 (plain v8, tpb=256, 512 CTAs) = best ncu: DRAM=84.8%, 114.2us.
// R8 (tpb=128) regressed -> grid axis closed. This round adds evict-first
// (.cs) to the 256-bit loads/stores: 768 MB streamed through 126 MB L2
// with zero reuse; evict-first reduces read-vs-write sector thrash.
// Everything else identical to R7.

static constexpr int B  = 16;
static constexpr int T  = 64;
static constexpr int N  = 65536;
static constexpr int N8 = N / 8;     // float8 lanes per (b, t) row = 8192

__device__ __forceinline__ void ldg256_cs(const float* p, float* v) {
    asm volatile(
        "ld.global.cs.v8.f32 {%0, %1, %2, %3, %4, %5, %6, %7}, [%8];"
        : "=f"(v[0]), "=f"(v[1]), "=f"(v[2]), "=f"(v[3]),
          "=f"(v[4]), "=f"(v[5]), "=f"(v[6]), "=f"(v[7])
        : "l"(p));
}

__device__ __forceinline__ void stg256_cs(float* p, const float* v) {
    asm volatile(
        "st.global.cs.v8.f32 [%0], {%1, %2, %3, %4, %5, %6, %7, %8};"
        :: "l"(p),
           "f"(v[0]), "f"(v[1]), "f"(v[2]), "f"(v[3]),
           "f"(v[4]), "f"(v[5]), "f"(v[6]), "f"(v[7])
        : "memory");
}

__global__ __launch_bounds__(256) void lif_kernel(
    const float* __restrict__ x,
    const float* __restrict__ noise,
    float* __restrict__ out)
{
    int idx = blockIdx.x * blockDim.x + threadIdx.x;   // 0 .. B*N8-1 (exact)

    int b  = idx >> 13;          // / N8 (8192)
    int n8 = idx & (N8 - 1);     // % N8

    const size_t base = (size_t)b * T * N + (size_t)n8 * 8;
    const float* __restrict__ xp = x     + base;
    const float* __restrict__ np = noise + base;
    float*       __restrict__ op = out   + base;

    float u[8];
#pragma unroll
    for (int i = 0; i < 8; i++) u[i] = 0.f;

#pragma unroll
    for (int t = 0; t < T; t++) {
        float xv[8], nv[8], o[8];
        ldg256_cs(xp + (size_t)t * N, xv);
        ldg256_cs(np + (size_t)t * N, nv);

#pragma unroll
        for (int i = 0; i < 8; i++) {
            u[i] = fmaf(-0.5f, nv[i], fmaf(0.5f, u[i], xv[i]));
            o[i] = (u[i] > 1.0f) ? 1.0f : 0.0f;
            u[i] = (u[i] > 1.0f) ? 0.0f : u[i];
        }

        stg256_cs(op + (size_t)t * N, o);
    }
}

extern "C" void kernel_launch(void* const* d_in, const int* in_sizes, int n_in,
                              void* d_out, int out_size)
{
    const float* x     = (const float*)d_in[0];
    const float* noise = (const float*)d_in[1];
    float*       out   = (float*)d_out;

    const int total_threads = B * N8;        // 131072
    const int tpb = 256;
    const int blocks = total_threads / tpb;  // 512, exact

    lif_kernel<<<blocks, tpb>>>(x, noise, out);
}